// round 1
// baseline (speedup 1.0000x reference)
#include <cuda_runtime.h>

#define NT 8192          // true rows
#define NP 8192          // pred cols
#define CAP 32           // max candidates kept per row (expected ~2, Poisson tail safe)
#define MAXC 16384       // max total compacted candidates (expected ~9K)

// Scratch (device globals — allocation-free per harness rules)
__device__ unsigned long long g_cand[NT * CAP];   // key = (f32bits(d) << 13) | j
__device__ int g_cnt[NT];

// ---------------------------------------------------------------------------
// Phase 1: candidate generation. grid (32 row-blocks, 8 col-chunks), 256 thr.
// Each thread owns one true row; pred col-chunk (1024 pts) cached in smem.
// ---------------------------------------------------------------------------
__global__ __launch_bounds__(256) void build_cand(const float4* __restrict__ pred,
                                                  const float4* __restrict__ tru) {
    __shared__ float4 sp[1024];
    const int colBase = blockIdx.y * 1024;
    for (int k = threadIdx.x; k < 1024; k += 256) sp[k] = pred[colBase + k];
    __syncthreads();

    const int row = blockIdx.x * 256 + threadIdx.x;
    const float4 t = tru[row];
    if (t.w < 0.5f) return;   // !true_occ -> no valid pairs for this row

#pragma unroll 4
    for (int k = 0; k < 1024; k++) {
        const float4 p = sp[k];
        const float dx = t.x - p.x, dy = t.y - p.y, dz = t.z - p.z;
        float d2 = dx * dx;
        d2 = fmaf(dy, dy, d2);
        d2 = fmaf(dz, dz, d2);
        // cheap prefilter with +2ulp slack, then exact ref-style check d<=1.0
        if (p.w >= 0.5f && d2 <= 1.0000002f) {
            const float d = __fsqrt_rn(d2);
            if (d <= 1.0f) {
                const int idx = atomicAdd(&g_cnt[row], 1);
                if (idx < CAP) {
                    g_cand[row * CAP + idx] =
                        (((unsigned long long)__float_as_uint(d)) << 13) |
                        (unsigned)(colBase + k);
                }
            }
        }
    }
}

// ---------------------------------------------------------------------------
// Phase 2: compact candidates into smem, then serial greedy replay (thread 0).
// Dynamic smem layout (bytes):
//   [0,      131072) s_cand   u64[16384]   (first 8KB reused as scan buffer)
//   [131072, 163840) s_pp     f32[8192]    pred probabilities
//   [163840, 196608) s_tp     f32[8192]    true probabilities
//   [196608, 229380) s_meta   u32[8193]    (row<<15 | offset), + sentinel
//   [229380, 230404) s_mask   u32[256]     matched-column bitmask
//   [230404, 230408) s_occ    i32
//   [230408, 230416) s_tot    u64
// ---------------------------------------------------------------------------
#define SMEM_BYTES 230416

__global__ __launch_bounds__(1024, 1) void greedy_match(const float4* __restrict__ pred,
                                                        const float4* __restrict__ tru,
                                                        float* __restrict__ out) {
    extern __shared__ unsigned char sm[];
    unsigned long long* s_cand = (unsigned long long*)sm;
    float*    s_pp   = (float*)(sm + 131072);
    float*    s_tp   = (float*)(sm + 163840);
    unsigned* s_meta = (unsigned*)(sm + 196608);
    unsigned* s_mask = (unsigned*)(sm + 229380);
    int*      s_occ  = (int*)(sm + 230404);
    unsigned long long* s_tot  = (unsigned long long*)(sm + 230408);
    unsigned long long* s_scan = (unsigned long long*)sm;  // alias: used before s_cand fill

    const int tid = threadIdx.x;

    // Load probabilities; count true occupancy.
    int occ = 0;
    for (int i = tid; i < NT; i += 1024) {
        s_pp[i] = pred[i].w;
        const float tp = tru[i].w;
        s_tp[i] = tp;
        occ += (tp >= 0.5f) ? 1 : 0;
    }
    if (tid < 256) s_mask[tid] = 0u;
    if (tid == 0) *s_occ = 0;
    __syncthreads();
    atomicAdd(s_occ, occ);

    // Per-thread counts for 8 consecutive rows; pack (nonempty, count) totals.
    int c[8];
    int csum = 0, bsum = 0;
    const int rbase = tid * 8;
#pragma unroll
    for (int q = 0; q < 8; q++) {
        int cc = g_cnt[rbase + q];
        cc = min(cc, CAP);
        c[q] = cc;
        csum += cc;
        bsum += (cc > 0) ? 1 : 0;
    }
    s_scan[tid] = (((unsigned long long)(unsigned)bsum) << 32) | (unsigned)csum;
    __syncthreads();

    // Hillis–Steele inclusive scan over 1024 packed pairs.
    for (int ofs = 1; ofs < 1024; ofs <<= 1) {
        const unsigned long long v = s_scan[tid];
        const unsigned long long a = (tid >= ofs) ? s_scan[tid - ofs] : 0ULL;
        __syncthreads();
        s_scan[tid] = v + a;
        __syncthreads();
    }
    const unsigned long long excl = (tid > 0) ? s_scan[tid - 1] : 0ULL;
    const unsigned long long tot  = s_scan[1023];
    __syncthreads();  // scan buffer dead; s_cand region reusable from here

    // Compact: copy each nonempty row's candidates; emit meta in row order.
    int coff = (int)(excl & 0xFFFFFFFFu);
    int bidx = (int)(excl >> 32);
#pragma unroll
    for (int q = 0; q < 8; q++) {
        const int cc = c[q];
        if (cc > 0) {
            const int row = rbase + q;
            const int start = coff;
            s_meta[bidx] = ((unsigned)row << 15) | (unsigned)min(start, MAXC);
            for (int e = 0; e < cc; e++) {
                const int dst = start + e;
                if (dst < MAXC) s_cand[dst] = g_cand[row * CAP + e];
            }
            coff += cc;
            bidx++;
        }
    }
    if (tid == 1023) {
        const int btot = (int)(tot >> 32);
        const int ctot = (int)(tot & 0xFFFFFFFFu);
        s_meta[btot] = (unsigned)min(ctot, MAXC);  // sentinel end offset
        *s_tot = tot;
    }
    __syncthreads();

    // Serial greedy replay over nonempty rows only (exact reference order).
    if (tid == 0) {
        const int ncomp = (int)((*s_tot) >> 32);
        float sum_d = 0.0f, sum_p = 0.0f;
        int nm = 0;
        for (int k = 0; k < ncomp; k++) {
            const unsigned m0 = s_meta[k];
            const unsigned m1 = s_meta[k + 1];
            const int row = (int)(m0 >> 15);
            const int off = (int)(m0 & 0x7FFFu);
            const int end = (int)(m1 & 0x7FFFu);
            unsigned long long best = ~0ULL;
            for (int e = off; e < end; e++) {
                const unsigned long long cd = s_cand[e];
                const unsigned j = (unsigned)cd & 8191u;
                if (!((s_mask[j >> 5] >> (j & 31u)) & 1u)) {
                    if (cd < best) best = cd;
                }
            }
            if (best != ~0ULL) {
                const unsigned j = (unsigned)best & 8191u;
                s_mask[j >> 5] |= (1u << (j & 31u));
                const float d = __uint_as_float((unsigned)(best >> 13));
                sum_d += d;
                nm++;
                const float dp = s_tp[row] - s_pp[j];
                sum_p = fmaf(dp, dp, sum_p);
            }
        }
        const float fnm = (float)nm;
        const float unm = (float)(*s_occ) - fnm;
        const float mean_dist = sum_d / fnm;
        const float prob_mse  = sum_p / fnm;
        const float spatial_error = mean_dist + 10.0f * unm;
        const float prob_error    = prob_mse + unm;
        out[0] = spatial_error + prob_error;
    }
}

// ---------------------------------------------------------------------------
extern "C" void kernel_launch(void* const* d_in, const int* in_sizes, int n_in,
                              void* d_out, int out_size) {
    const float4* pred = (const float4*)d_in[0];
    const float4* tru  = (const float4*)d_in[1];
    float* out = (float*)d_out;

    void* cntp = nullptr;
    cudaGetSymbolAddress(&cntp, g_cnt);
    cudaMemsetAsync(cntp, 0, NT * sizeof(int));

    build_cand<<<dim3(32, 8), 256>>>(pred, tru);

    cudaFuncSetAttribute(greedy_match, cudaFuncAttributeMaxDynamicSharedMemorySize,
                         SMEM_BYTES);
    greedy_match<<<1, 1024, SMEM_BYTES>>>(pred, tru, out);
}

// round 2
// speedup vs baseline: 6.7269x; 6.7269x over previous
#include <cuda_runtime.h>

#define NT 8192          // true rows
#define NP 8192          // pred cols
#define CAP 32           // max candidates kept per row (expected ~2, Poisson tail safe)
#define MAXC 16384       // max total compacted candidates (expected ~7.5K)

// Scratch (device globals — allocation-free per harness rules)
__device__ unsigned long long g_cand[NT * CAP];   // key = (f32bits(d) << 13) | j
__device__ int g_cnt[NT];

// ---------------------------------------------------------------------------
// Phase 1: candidate generation. grid (32 row-blocks, 8 col-chunks), 256 thr.
// ---------------------------------------------------------------------------
__global__ __launch_bounds__(256) void build_cand(const float4* __restrict__ pred,
                                                  const float4* __restrict__ tru) {
    __shared__ float4 sp[1024];
    const int colBase = blockIdx.y * 1024;
    for (int k = threadIdx.x; k < 1024; k += 256) sp[k] = pred[colBase + k];
    __syncthreads();

    const int row = blockIdx.x * 256 + threadIdx.x;
    const float4 t = tru[row];
    if (t.w < 0.5f) return;   // !true_occ -> no valid pairs for this row

#pragma unroll 4
    for (int k = 0; k < 1024; k++) {
        const float4 p = sp[k];
        const float dx = t.x - p.x, dy = t.y - p.y, dz = t.z - p.z;
        float d2 = dx * dx;
        d2 = fmaf(dy, dy, d2);
        d2 = fmaf(dz, dz, d2);
        if (p.w >= 0.5f && d2 <= 1.0000002f) {
            const float d = __fsqrt_rn(d2);
            if (d <= 1.0f) {
                const int idx = atomicAdd(&g_cnt[row], 1);
                if (idx < CAP) {
                    g_cand[row * CAP + idx] =
                        (((unsigned long long)__float_as_uint(d)) << 13) |
                        (unsigned)(colBase + k);
                }
            }
        }
    }
}

// ---------------------------------------------------------------------------
// Phase 2: compact candidates into smem, then PARALLEL round-based greedy.
// Exactly reproduces the sequential greedy matching:
//   round: every unresolved row registers atomicMin(colmin[j], k) on all its
//   unclaimed candidate columns; a row confirms its min-key candidate j iff
//   colmin[j]==k (no earlier unresolved row wants j -> j survives to its turn,
//   and min over a superset that stays available is still its greedy pick).
//
// Dynamic smem layout (bytes):
//   [0,      131072) s_cand   u64[16384]  (first 8KB reused as scan buffer)
//   [131072, 163844) s_meta   u32[8193]   (row<<15 | offset), + sentinel
//   [163848, 196616) s_colmin u32[8192]
//   [196616, 197640) s_claim  u32[256]    matched-column bitmask
//   [197640, ...)    s_nleft, s_occ, s_tot, reduction buffers
// ---------------------------------------------------------------------------
#define SMEM_BYTES 198144

__global__ __launch_bounds__(1024, 1) void greedy_match(const float4* __restrict__ pred,
                                                        const float4* __restrict__ tru,
                                                        float* __restrict__ out) {
    extern __shared__ unsigned char sm[];
    unsigned long long* s_cand   = (unsigned long long*)sm;
    unsigned*           s_meta   = (unsigned*)(sm + 131072);
    unsigned*           s_colmin = (unsigned*)(sm + 163848);
    unsigned*           s_claim  = (unsigned*)(sm + 196616);
    int*                s_nleft  = (int*)(sm + 197640);
    int*                s_occ    = (int*)(sm + 197644);
    unsigned long long* s_tot    = (unsigned long long*)(sm + 197648);
    float*              s_rd     = (float*)(sm + 197656);           // [32]
    float*              s_rp     = (float*)(sm + 197784);           // [32]
    int*                s_rn     = (int*)(sm + 197912);             // [32]
    unsigned long long* s_scan   = (unsigned long long*)sm;         // alias (pre-fill)

    const int tid  = threadIdx.x;
    const int lane = tid & 31;
    const int wid  = tid >> 5;

    // --- occupancy count over true cloud ---
    const float* truf = (const float*)tru;
    int occ = 0;
    for (int i = tid; i < NT; i += 1024) occ += (truf[4 * i + 3] >= 0.5f) ? 1 : 0;
#pragma unroll
    for (int o = 16; o > 0; o >>= 1) occ += __shfl_down_sync(0xFFFFFFFFu, occ, o);
    if (tid < 256) s_claim[tid] = 0u;
    if (tid == 0) { *s_occ = 0; }
    __syncthreads();
    if (lane == 0) atomicAdd(s_occ, occ);

    // --- per-thread counts for 8 consecutive rows; pack (nonempty, count) ---
    int c[8];
    int csum = 0, bsum = 0;
    const int rbase = tid * 8;
#pragma unroll
    for (int q = 0; q < 8; q++) {
        int cc = g_cnt[rbase + q];
        cc = min(cc, CAP);
        c[q] = cc;
        csum += cc;
        bsum += (cc > 0) ? 1 : 0;
    }
    s_scan[tid] = (((unsigned long long)(unsigned)bsum) << 32) | (unsigned)csum;
    __syncthreads();

    // Hillis–Steele inclusive scan over 1024 packed pairs.
    for (int ofs = 1; ofs < 1024; ofs <<= 1) {
        const unsigned long long v = s_scan[tid];
        const unsigned long long a = (tid >= ofs) ? s_scan[tid - ofs] : 0ULL;
        __syncthreads();
        s_scan[tid] = v + a;
        __syncthreads();
    }
    const unsigned long long excl = (tid > 0) ? s_scan[tid - 1] : 0ULL;
    const unsigned long long tot  = s_scan[1023];
    if (tid == 1023) *s_tot = tot;
    __syncthreads();  // scan buffer dead; s_cand region reusable from here

    // --- compaction: copy nonempty rows' candidates; meta in row order ---
    int coff = (int)(excl & 0xFFFFFFFFu);
    int bidx = (int)(excl >> 32);
#pragma unroll
    for (int q = 0; q < 8; q++) {
        const int cc = c[q];
        if (cc > 0) {
            const int row = rbase + q;
            const int start = coff;
            s_meta[bidx] = ((unsigned)row << 15) | (unsigned)min(start, MAXC);
            for (int e = 0; e < cc; e++) {
                const int dst = start + e;
                if (dst < MAXC) s_cand[dst] = g_cand[row * CAP + e];
            }
            coff += cc;
            bidx++;
        }
    }
    if (tid == 1023) {
        const int btot = (int)(tot >> 32);
        const int ctot = (int)(tot & 0xFFFFFFFFu);
        s_meta[btot] = (unsigned)min(ctot, MAXC);  // sentinel end offset
    }
    __syncthreads();

    const int ncomp = (int)((*s_tot) >> 32);

    // --- round-based parallel greedy (thread t owns rows t, t+1024, ...) ---
    unsigned rowsolved = 0, rowmatched = 0;   // 8-bit flags in registers
    while (true) {
        for (int i = tid; i < NP; i += 1024) s_colmin[i] = 0xFFFFFFFFu;
        if (tid == 0) *s_nleft = 0;
        __syncthreads();

        // pass A: register on all unclaimed candidate columns
#pragma unroll
        for (int r = 0; r < 8; r++) {
            const int k = tid + (r << 10);
            if (k >= ncomp || ((rowsolved >> r) & 1u)) continue;
            const int off = (int)(s_meta[k] & 0x7FFFu);
            const int end = (int)(s_meta[k + 1] & 0x7FFFu);
            for (int e = off; e < end; e++) {
                const unsigned j = (unsigned)s_cand[e] & 8191u;
                if (!((s_claim[j >> 5] >> (j & 31u)) & 1u))
                    atomicMin(&s_colmin[j], (unsigned)k);
            }
        }
        __syncthreads();

        // pass B: confirm min-key candidate if this row is the min registrant
        int left = 0;
#pragma unroll
        for (int r = 0; r < 8; r++) {
            const int k = tid + (r << 10);
            if (k >= ncomp || ((rowsolved >> r) & 1u)) continue;
            const int off = (int)(s_meta[k] & 0x7FFFu);
            const int end = (int)(s_meta[k + 1] & 0x7FFFu);
            unsigned long long best = ~0ULL;
            for (int e = off; e < end; e++) {
                const unsigned long long cd = s_cand[e];
                const unsigned j = (unsigned)cd & 8191u;
                if (!((s_claim[j >> 5] >> (j & 31u)) & 1u) && cd < best) best = cd;
            }
            if (best == ~0ULL) {
                rowsolved |= 1u << r;            // unmatched
            } else {
                const unsigned j = (unsigned)best & 8191u;
                if (s_colmin[j] == (unsigned)k) {
                    atomicOr(&s_claim[j >> 5], 1u << (j & 31u));
                    rowsolved |= 1u << r;
                    rowmatched |= 1u << r;
                    s_cand[off] = best;          // park result in own slot 0
                } else {
                    left++;
                }
            }
        }
        if (left) atomicAdd(s_nleft, left);
        __syncthreads();
        if (*s_nleft == 0) break;
        __syncthreads();   // protect colmin reset vs. this round's reads
    }

    // --- deterministic fixed-order accumulation ---
    const float* predf = (const float*)pred;
    float sd = 0.0f, sp = 0.0f;
    int nm = 0;
#pragma unroll
    for (int r = 0; r < 8; r++) {
        const int k = tid + (r << 10);
        if (k >= ncomp || !((rowmatched >> r) & 1u)) continue;
        const unsigned m0 = s_meta[k];
        const int off = (int)(m0 & 0x7FFFu);
        const int row = (int)(m0 >> 15);
        const unsigned long long best = s_cand[off];
        const unsigned j = (unsigned)best & 8191u;
        sd += __uint_as_float((unsigned)(best >> 13));
        nm++;
        const float dp = truf[4 * row + 3] - predf[4 * j + 3];
        sp = fmaf(dp, dp, sp);
    }
    // warp tree reduce
#pragma unroll
    for (int o = 16; o > 0; o >>= 1) {
        sd += __shfl_down_sync(0xFFFFFFFFu, sd, o);
        sp += __shfl_down_sync(0xFFFFFFFFu, sp, o);
        nm += __shfl_down_sync(0xFFFFFFFFu, nm, o);
    }
    if (lane == 0) { s_rd[wid] = sd; s_rp[wid] = sp; s_rn[wid] = nm; }
    __syncthreads();
    if (tid == 0) {
        float tsd = 0.0f, tsp = 0.0f;
        int tnm = 0;
        for (int w = 0; w < 32; w++) { tsd += s_rd[w]; tsp += s_rp[w]; tnm += s_rn[w]; }
        const float fnm = (float)tnm;
        const float unm = (float)(*s_occ) - fnm;
        const float mean_dist = tsd / fnm;
        const float prob_mse  = tsp / fnm;
        out[0] = (mean_dist + 10.0f * unm) + (prob_mse + unm);
    }
}

// ---------------------------------------------------------------------------
extern "C" void kernel_launch(void* const* d_in, const int* in_sizes, int n_in,
                              void* d_out, int out_size) {
    const float4* pred = (const float4*)d_in[0];
    const float4* tru  = (const float4*)d_in[1];
    float* out = (float*)d_out;

    void* cntp = nullptr;
    cudaGetSymbolAddress(&cntp, g_cnt);
    cudaMemsetAsync(cntp, 0, NT * sizeof(int));

    build_cand<<<dim3(32, 8), 256>>>(pred, tru);

    cudaFuncSetAttribute(greedy_match, cudaFuncAttributeMaxDynamicSharedMemorySize,
                         SMEM_BYTES);
    greedy_match<<<1, 1024, SMEM_BYTES>>>(pred, tru, out);
}

// round 3
// speedup vs baseline: 8.0635x; 1.1987x over previous
#include <cuda_runtime.h>

#define NT 8192          // true rows
#define NP 8192          // pred cols
#define CAP 32           // max candidates kept per row
#define MAXC 16384       // max total compacted candidates (expected ~7.5K)
#define NCELL 8000       // 20x20x20 unit cells

// Scratch (device globals — allocation-free per harness rules)
__device__ unsigned long long g_cand[NT * CAP];   // key = (f32bits(d) << 13) | j
__device__ int g_cnt[NT];
__device__ int g_cellcnt[NCELL];
__device__ int g_cellstart[NCELL];
__device__ int g_cursor[NCELL];
__device__ float4 g_pts[NP];     // occupied preds, cell-sorted: xyz + j as int bits
__device__ int g_occ;            // count of occupied true points

__device__ __forceinline__ int cell_of(float x, float y, float z) {
    const int cx = min(19, (int)x);
    const int cy = min(19, (int)y);
    const int cz = min(19, (int)z);
    return (cx * 20 + cy) * 20 + cz;
}

// ---------------------------------------------------------------------------
// Phase 1a: count occupied preds per cell.
// ---------------------------------------------------------------------------
__global__ __launch_bounds__(256) void cell_count(const float4* __restrict__ pred) {
    const int i = blockIdx.x * 256 + threadIdx.x;
    const float4 p = pred[i];
    if (p.w >= 0.5f) atomicAdd(&g_cellcnt[cell_of(p.x, p.y, p.z)], 1);
}

// ---------------------------------------------------------------------------
// Phase 1b: exclusive scan of cell counts (1 block, 1024 thr, 8 cells/thr).
// ---------------------------------------------------------------------------
__global__ __launch_bounds__(1024) void cell_scan() {
    __shared__ int s_w[32];
    const int tid = threadIdx.x, lane = tid & 31, wid = tid >> 5;
    const int base = tid * 8;
    int v[8], pre[8], s = 0;
#pragma unroll
    for (int q = 0; q < 8; q++) {
        const int c = base + q;
        v[q] = (c < NCELL) ? g_cellcnt[c] : 0;
        pre[q] = s;
        s += v[q];
    }
    int inc = s;
#pragma unroll
    for (int o = 1; o < 32; o <<= 1) {
        const int n = __shfl_up_sync(0xFFFFFFFFu, inc, o);
        if (lane >= o) inc += n;
    }
    if (lane == 31) s_w[wid] = inc;
    __syncthreads();
    if (wid == 0) {
        int w = s_w[lane];
#pragma unroll
        for (int o = 1; o < 32; o <<= 1) {
            const int n = __shfl_up_sync(0xFFFFFFFFu, w, o);
            if (lane >= o) w += n;
        }
        s_w[lane] = w;
    }
    __syncthreads();
    const int wex = wid ? s_w[wid - 1] : 0;
    const int texcl = wex + inc - s;
#pragma unroll
    for (int q = 0; q < 8; q++) {
        const int c = base + q;
        if (c < NCELL) {
            const int st = texcl + pre[q];
            g_cellstart[c] = st;
            g_cursor[c] = st;
        }
    }
    if (tid == 0) g_occ = 0;
}

// ---------------------------------------------------------------------------
// Phase 1c: scatter occupied preds into cell-sorted array.
// ---------------------------------------------------------------------------
__global__ __launch_bounds__(256) void cell_scatter(const float4* __restrict__ pred) {
    const int i = blockIdx.x * 256 + threadIdx.x;
    const float4 p = pred[i];
    if (p.w >= 0.5f) {
        const int pos = atomicAdd(&g_cursor[cell_of(p.x, p.y, p.z)], 1);
        g_pts[pos] = make_float4(p.x, p.y, p.z, __int_as_float(i));
    }
}

// ---------------------------------------------------------------------------
// Phase 1d: candidate generation via 3x3x3 neighbor cells. One thread per row.
// Also accumulates true-occupancy count into g_occ.
// ---------------------------------------------------------------------------
__global__ __launch_bounds__(256) void build_cand(const float4* __restrict__ tru) {
    __shared__ int s_occ;
    if (threadIdx.x == 0) s_occ = 0;
    __syncthreads();

    const int row = blockIdx.x * 256 + threadIdx.x;
    const float4 t = tru[row];
    const bool occ = (t.w >= 0.5f);
    int cnt = 0;
    if (occ) {
        const int cx = min(19, (int)t.x);
        const int cy = min(19, (int)t.y);
        const int cz = min(19, (int)t.z);
        const int x0 = max(0, cx - 1), x1 = min(19, cx + 1);
        const int y0 = max(0, cy - 1), y1 = min(19, cy + 1);
        const int z0 = max(0, cz - 1), z1 = min(19, cz + 1);
        for (int X = x0; X <= x1; X++)
            for (int Y = y0; Y <= y1; Y++) {
                const int crow = (X * 20 + Y) * 20;
                for (int Z = z0; Z <= z1; Z++) {
                    const int c = crow + Z;
                    const int st = g_cellstart[c];
                    const int en = st + g_cellcnt[c];
                    for (int i = st; i < en; i++) {
                        const float4 p = g_pts[i];
                        const float dx = t.x - p.x, dy = t.y - p.y, dz = t.z - p.z;
                        float d2 = dx * dx;
                        d2 = fmaf(dy, dy, d2);
                        d2 = fmaf(dz, dz, d2);
                        if (d2 <= 1.0000002f) {
                            const float d = __fsqrt_rn(d2);
                            if (d <= 1.0f) {
                                if (cnt < CAP)
                                    g_cand[row * CAP + cnt] =
                                        (((unsigned long long)__float_as_uint(d)) << 13) |
                                        (unsigned)__float_as_int(p.w);
                                cnt++;
                            }
                        }
                    }
                }
            }
    }
    g_cnt[row] = min(cnt, CAP);

    const unsigned b = __ballot_sync(0xFFFFFFFFu, occ);
    if ((threadIdx.x & 31) == 0) atomicAdd(&s_occ, __popc(b));
    __syncthreads();
    if (threadIdx.x == 0) atomicAdd(&g_occ, s_occ);
}

// ---------------------------------------------------------------------------
// Phase 2: compact candidates into smem, then PARALLEL round-based greedy.
// Exactly reproduces the sequential greedy matching (see round-2 argument):
// a row confirms its min-key unclaimed candidate j iff no unresolved earlier
// row also has j among its unclaimed candidates (colmin[j]==k).
//
// Dynamic smem layout (bytes):
//   [0,      131072) s_cand   u64[16384]
//   [131072, 163844) s_meta   u32[8193]   (row<<15 | offset), + sentinel
//   [163848, 196616) s_colmin u32[8192]
//   [196616, 197640) s_claim  u32[256]    matched-column bitmask
//   [197640, ...)    s_nleft, reduction buffers, warp-scan buffer
// ---------------------------------------------------------------------------
#define SMEM_BYTES 198448

__global__ __launch_bounds__(1024, 1) void greedy_match(const float4* __restrict__ pred,
                                                        const float4* __restrict__ tru,
                                                        float* __restrict__ out) {
    extern __shared__ unsigned char sm[];
    unsigned long long* s_cand   = (unsigned long long*)sm;
    unsigned*           s_meta   = (unsigned*)(sm + 131072);
    unsigned*           s_colmin = (unsigned*)(sm + 163848);
    unsigned*           s_claim  = (unsigned*)(sm + 196616);
    int*                s_nleft  = (int*)(sm + 197640);
    float*              s_rd     = (float*)(sm + 197648);           // [32]
    float*              s_rp     = (float*)(sm + 197776);           // [32]
    int*                s_rn     = (int*)(sm + 197904);             // [32]
    unsigned long long* s_wsum   = (unsigned long long*)(sm + 198064); // [32] u64

    const int tid  = threadIdx.x;
    const int lane = tid & 31;
    const int wid  = tid >> 5;

    if (tid < 256) s_claim[tid] = 0u;

    // --- per-thread counts for 8 consecutive rows; pack (nonempty, count) ---
    int c[8];
    int csum = 0, bsum = 0;
    const int rbase = tid * 8;
#pragma unroll
    for (int q = 0; q < 8; q++) {
        const int cc = g_cnt[rbase + q];
        c[q] = cc;
        csum += cc;
        bsum += (cc > 0) ? 1 : 0;
    }

    // --- shuffle-based inclusive scan over 1024 packed (nonempty,count) ---
    const unsigned long long val =
        (((unsigned long long)(unsigned)bsum) << 32) | (unsigned)csum;
    unsigned long long inc = val;
#pragma unroll
    for (int o = 1; o < 32; o <<= 1) {
        const unsigned long long n = __shfl_up_sync(0xFFFFFFFFu, inc, o);
        if (lane >= o) inc += n;
    }
    if (lane == 31) s_wsum[wid] = inc;
    __syncthreads();
    if (wid == 0) {
        unsigned long long w = s_wsum[lane];
#pragma unroll
        for (int o = 1; o < 32; o <<= 1) {
            const unsigned long long n = __shfl_up_sync(0xFFFFFFFFu, w, o);
            if (lane >= o) w += n;
        }
        s_wsum[lane] = w;
    }
    __syncthreads();
    const unsigned long long wex = wid ? s_wsum[wid - 1] : 0ULL;
    const unsigned long long excl = wex + inc - val;
    const unsigned long long tot  = s_wsum[31];

    // --- compaction: copy nonempty rows' candidates; meta in row order ---
    int coff = (int)(excl & 0xFFFFFFFFu);
    int bidx = (int)(excl >> 32);
#pragma unroll
    for (int q = 0; q < 8; q++) {
        const int cc = c[q];
        if (cc > 0) {
            const int row = rbase + q;
            const int start = coff;
            s_meta[bidx] = ((unsigned)row << 15) | (unsigned)min(start, MAXC);
            for (int e = 0; e < cc; e++) {
                const int dst = start + e;
                if (dst < MAXC) s_cand[dst] = g_cand[row * CAP + e];
            }
            coff += cc;
            bidx++;
        }
    }
    const int ncomp = (int)(tot >> 32);
    if (tid == 0) {
        const int ctot = (int)(tot & 0xFFFFFFFFu);
        s_meta[ncomp] = (unsigned)min(ctot, MAXC);  // sentinel end offset
    }
    __syncthreads();

    // --- round-based parallel greedy (thread t owns rows t, t+1024, ...) ---
    unsigned rowsolved = 0, rowmatched = 0;   // 8-bit flags in registers
    while (true) {
        for (int i = tid; i < NP; i += 1024) s_colmin[i] = 0xFFFFFFFFu;
        if (tid == 0) *s_nleft = 0;
        __syncthreads();

        // pass A: register on all unclaimed candidate columns
#pragma unroll
        for (int r = 0; r < 8; r++) {
            const int k = tid + (r << 10);
            if (k >= ncomp || ((rowsolved >> r) & 1u)) continue;
            const int off = (int)(s_meta[k] & 0x7FFFu);
            const int end = (int)(s_meta[k + 1] & 0x7FFFu);
            for (int e = off; e < end; e++) {
                const unsigned j = (unsigned)s_cand[e] & 8191u;
                if (!((s_claim[j >> 5] >> (j & 31u)) & 1u))
                    atomicMin(&s_colmin[j], (unsigned)k);
            }
        }
        __syncthreads();

        // pass B: confirm min-key candidate if this row is the min registrant
        int left = 0;
#pragma unroll
        for (int r = 0; r < 8; r++) {
            const int k = tid + (r << 10);
            if (k >= ncomp || ((rowsolved >> r) & 1u)) continue;
            const int off = (int)(s_meta[k] & 0x7FFFu);
            const int end = (int)(s_meta[k + 1] & 0x7FFFu);
            unsigned long long best = ~0ULL;
            for (int e = off; e < end; e++) {
                const unsigned long long cd = s_cand[e];
                const unsigned j = (unsigned)cd & 8191u;
                if (!((s_claim[j >> 5] >> (j & 31u)) & 1u) && cd < best) best = cd;
            }
            if (best == ~0ULL) {
                rowsolved |= 1u << r;            // unmatched
            } else {
                const unsigned j = (unsigned)best & 8191u;
                if (s_colmin[j] == (unsigned)k) {
                    atomicOr(&s_claim[j >> 5], 1u << (j & 31u));
                    rowsolved |= 1u << r;
                    rowmatched |= 1u << r;
                    s_cand[off] = best;          // park result in own slot 0
                } else {
                    left++;
                }
            }
        }
        if (left) atomicAdd(s_nleft, left);
        __syncthreads();
        if (*s_nleft == 0) break;
        __syncthreads();   // protect colmin reset vs. this round's reads
    }

    // --- deterministic fixed-order accumulation ---
    const float* truf  = (const float*)tru;
    const float* predf = (const float*)pred;
    float sd = 0.0f, sp = 0.0f;
    int nm = 0;
#pragma unroll
    for (int r = 0; r < 8; r++) {
        const int k = tid + (r << 10);
        if (k >= ncomp || !((rowmatched >> r) & 1u)) continue;
        const unsigned m0 = s_meta[k];
        const int off = (int)(m0 & 0x7FFFu);
        const int row = (int)(m0 >> 15);
        const unsigned long long best = s_cand[off];
        const unsigned j = (unsigned)best & 8191u;
        sd += __uint_as_float((unsigned)(best >> 13));
        nm++;
        const float dp = truf[4 * row + 3] - predf[4 * j + 3];
        sp = fmaf(dp, dp, sp);
    }
#pragma unroll
    for (int o = 16; o > 0; o >>= 1) {
        sd += __shfl_down_sync(0xFFFFFFFFu, sd, o);
        sp += __shfl_down_sync(0xFFFFFFFFu, sp, o);
        nm += __shfl_down_sync(0xFFFFFFFFu, nm, o);
    }
    if (lane == 0) { s_rd[wid] = sd; s_rp[wid] = sp; s_rn[wid] = nm; }
    __syncthreads();
    if (tid == 0) {
        float tsd = 0.0f, tsp = 0.0f;
        int tnm = 0;
        for (int w = 0; w < 32; w++) { tsd += s_rd[w]; tsp += s_rp[w]; tnm += s_rn[w]; }
        const float fnm = (float)tnm;
        const float unm = (float)g_occ - fnm;
        const float mean_dist = tsd / fnm;
        const float prob_mse  = tsp / fnm;
        out[0] = (mean_dist + 10.0f * unm) + (prob_mse + unm);
    }
}

// ---------------------------------------------------------------------------
extern "C" void kernel_launch(void* const* d_in, const int* in_sizes, int n_in,
                              void* d_out, int out_size) {
    const float4* pred = (const float4*)d_in[0];
    const float4* tru  = (const float4*)d_in[1];
    float* out = (float*)d_out;

    void* ccp = nullptr;
    cudaGetSymbolAddress(&ccp, g_cellcnt);
    cudaMemsetAsync(ccp, 0, NCELL * sizeof(int));

    cell_count<<<32, 256>>>(pred);
    cell_scan<<<1, 1024>>>();
    cell_scatter<<<32, 256>>>(pred);
    build_cand<<<32, 256>>>(tru);

    cudaFuncSetAttribute(greedy_match, cudaFuncAttributeMaxDynamicSharedMemorySize,
                         SMEM_BYTES);
    greedy_match<<<1, 1024, SMEM_BYTES>>>(pred, tru, out);
}

// round 4
// speedup vs baseline: 14.4441x; 1.7913x over previous
#include <cuda_runtime.h>

#define NT 8192          // true rows
#define NP 8192          // pred cols
#define CAP 32           // max candidates kept per row
#define MAXC 12288       // max total compacted candidates (expected ~8.8K, 37 sigma slack)
#define NCELL 8000       // 20x20x20 unit cells
#define CELLCAP 16       // slots per cell (lambda ~0.51 occupied/cell)

// Scratch (device globals — allocation-free per harness rules)
__device__ unsigned long long g_cand[NT * CAP];   // key = (f32bits(d) << 13) | j
__device__ int g_cnt[NT];
__device__ int g_cellcnt[NCELL];
__device__ float4 g_pts[NCELL * CELLCAP];  // xyz + pred index as int bits
__device__ int g_occ;                      // count of occupied true points

__device__ __forceinline__ int cell_of(float x, float y, float z) {
    const int cx = min(19, (int)x);
    const int cy = min(19, (int)y);
    const int cz = min(19, (int)z);
    return (cx * 20 + cy) * 20 + cz;
}

// ---------------------------------------------------------------------------
// Phase 1a: bin occupied preds into fixed-capacity cells (count + scatter).
// ---------------------------------------------------------------------------
__global__ __launch_bounds__(256) void bin_points(const float4* __restrict__ pred) {
    const int i = blockIdx.x * 256 + threadIdx.x;
    if (i == 0) g_occ = 0;
    const float4 p = pred[i];
    if (p.w >= 0.5f) {
        const int c = cell_of(p.x, p.y, p.z);
        const int idx = atomicAdd(&g_cellcnt[c], 1);
        if (idx < CELLCAP)
            g_pts[c * CELLCAP + idx] = make_float4(p.x, p.y, p.z, __int_as_float(i));
    }
}

// ---------------------------------------------------------------------------
// Phase 1b: candidate generation, WARP per true row; lane L<27 owns one of the
// 3x3x3 neighbor cells. Also accumulates true-occupancy into g_occ.
// ---------------------------------------------------------------------------
#define WPB 8   // warps per block
__global__ __launch_bounds__(256) void build_cand(const float4* __restrict__ tru) {
    __shared__ int s_cnt[WPB];
    __shared__ int s_occ;
    const int wip  = threadIdx.x >> 5;
    const int lane = threadIdx.x & 31;
    const int row  = blockIdx.x * WPB + wip;

    if (threadIdx.x == 0) s_occ = 0;
    if (lane == 0) s_cnt[wip] = 0;
    __syncthreads();

    const float4 t = tru[row];
    const bool occ = (t.w >= 0.5f);

    if (occ && lane < 27) {
        const int cx = min(19, (int)t.x);
        const int cy = min(19, (int)t.y);
        const int cz = min(19, (int)t.z);
        const int X = cx + lane / 9 - 1;
        const int Y = cy + (lane / 3) % 3 - 1;
        const int Z = cz + lane % 3 - 1;
        if (X >= 0 && X < 20 && Y >= 0 && Y < 20 && Z >= 0 && Z < 20) {
            const int c = (X * 20 + Y) * 20 + Z;
            const int cnt = min(g_cellcnt[c], CELLCAP);
            for (int e = 0; e < cnt; e++) {
                const float4 p = g_pts[c * CELLCAP + e];
                const float dx = t.x - p.x, dy = t.y - p.y, dz = t.z - p.z;
                float d2 = dx * dx;
                d2 = fmaf(dy, dy, d2);
                d2 = fmaf(dz, dz, d2);
                if (d2 <= 1.0000002f) {
                    const float d = __fsqrt_rn(d2);
                    if (d <= 1.0f) {
                        const int idx = atomicAdd(&s_cnt[wip], 1);
                        if (idx < CAP)
                            g_cand[row * CAP + idx] =
                                (((unsigned long long)__float_as_uint(d)) << 13) |
                                (unsigned)__float_as_int(p.w);
                    }
                }
            }
        }
    }
    __syncwarp();
    if (lane == 0) {
        g_cnt[row] = min(s_cnt[wip], CAP);
        if (occ) atomicAdd(&s_occ, 1);
    }
    __syncthreads();
    if (threadIdx.x == 0 && s_occ) atomicAdd(&g_occ, s_occ);
}

// ---------------------------------------------------------------------------
// Phase 2: compact candidates into smem, then PARALLEL round-based greedy with
// ping-pong active lists. Equivalence to the sequential greedy: an active row k
// confirms its min-key unclaimed candidate j iff colmin[j]==k, i.e. no earlier
// unresolved row holds j among its unclaimed candidates.
//
// Dynamic smem layout (bytes):
//   [0,      98304)  s_cand   u64[12288]
//   [98304,  131076) s_meta   u32[8193]   (row<<15 | offset), + sentinel
//   [131080, 163848) s_colmin u32[8192]
//   [163848, 164872) s_claim  u32[256]
//   [164872, 164880) s_na     i32[2]      (ping-pong next-count)
//   [164880, 165264) s_rd/s_rp/s_rn reduction [32] each
//   [165264, 165520) s_wsum   u64[32]
//   [165520, 198288) s_listA/s_listB u16[8192] each
//   [198288, 214672) s_res    u16[8192]   (best cand index, 0xFFFF = unmatched)
// ---------------------------------------------------------------------------
#define SMEM_BYTES 214672

__global__ __launch_bounds__(1024, 1) void greedy_match(const float4* __restrict__ pred,
                                                        const float4* __restrict__ tru,
                                                        float* __restrict__ out) {
    extern __shared__ unsigned char sm[];
    unsigned long long* s_cand   = (unsigned long long*)sm;
    unsigned*           s_meta   = (unsigned*)(sm + 98304);
    unsigned*           s_colmin = (unsigned*)(sm + 131080);
    unsigned*           s_claim  = (unsigned*)(sm + 163848);
    int*                s_na     = (int*)(sm + 164872);
    float*              s_rd     = (float*)(sm + 164880);
    float*              s_rp     = (float*)(sm + 165008);
    int*                s_rn     = (int*)(sm + 165136);
    unsigned long long* s_wsum   = (unsigned long long*)(sm + 165264);
    unsigned short*     s_listA  = (unsigned short*)(sm + 165520);
    unsigned short*     s_listB  = (unsigned short*)(sm + 181904);
    unsigned short*     s_res    = (unsigned short*)(sm + 198288);

    const int tid  = threadIdx.x;
    const int lane = tid & 31;
    const int wid  = tid >> 5;

    if (tid < 256) s_claim[tid] = 0u;

    // --- per-thread counts for 8 consecutive rows; pack (nonempty, count) ---
    int c[8];
    int csum = 0, bsum = 0;
    const int rbase = tid * 8;
#pragma unroll
    for (int q = 0; q < 8; q++) {
        const int cc = g_cnt[rbase + q];
        c[q] = cc;
        csum += cc;
        bsum += (cc > 0) ? 1 : 0;
    }

    // --- shuffle-based inclusive scan over 1024 packed (nonempty,count) ---
    const unsigned long long val =
        (((unsigned long long)(unsigned)bsum) << 32) | (unsigned)csum;
    unsigned long long inc = val;
#pragma unroll
    for (int o = 1; o < 32; o <<= 1) {
        const unsigned long long n = __shfl_up_sync(0xFFFFFFFFu, inc, o);
        if (lane >= o) inc += n;
    }
    if (lane == 31) s_wsum[wid] = inc;
    __syncthreads();
    if (wid == 0) {
        unsigned long long w = s_wsum[lane];
#pragma unroll
        for (int o = 1; o < 32; o <<= 1) {
            const unsigned long long n = __shfl_up_sync(0xFFFFFFFFu, w, o);
            if (lane >= o) w += n;
        }
        s_wsum[lane] = w;
    }
    __syncthreads();
    const unsigned long long wex = wid ? s_wsum[wid - 1] : 0ULL;
    const unsigned long long excl = wex + inc - val;
    const unsigned long long tot  = s_wsum[31];

    // --- compaction: copy nonempty rows' candidates; meta in row order ---
    int coff = (int)(excl & 0xFFFFFFFFu);
    int bidx = (int)(excl >> 32);
#pragma unroll
    for (int q = 0; q < 8; q++) {
        const int cc = c[q];
        if (cc > 0) {
            const int row = rbase + q;
            const int start = coff;
            s_meta[bidx] = ((unsigned)row << 15) | (unsigned)min(start, MAXC);
            for (int e = 0; e < cc; e++) {
                const int dst = start + e;
                if (dst < MAXC) s_cand[dst] = g_cand[row * CAP + e];
            }
            coff += cc;
            bidx++;
        }
    }
    const int ncomp = (int)(tot >> 32);
    if (tid == 0) {
        const int ctot = (int)(tot & 0xFFFFFFFFu);
        s_meta[ncomp] = (unsigned)min(ctot, MAXC);  // sentinel end offset
    }

    // --- init colmin + initial active list (all compacted rows) ---
    for (int i = tid; i < NP; i += 1024) s_colmin[i] = 0xFFFFFFFFu;
    for (int k = tid; k < ncomp; k += 1024) s_listA[k] = (unsigned short)k;
    __syncthreads();

    unsigned short* cur = s_listA;
    unsigned short* nxt = s_listB;
    int n = ncomp;
    int par = 0;
    while (n > 0) {
        // pass A: each active row registers on ALL its candidate columns.
        // (registering on a claimed column is harmless: nobody reads it.)
        for (int i = tid; i < n; i += 1024) {
            const int k = cur[i];
            const int off = (int)(s_meta[k] & 0x7FFFu);
            const int end = (int)(s_meta[k + 1] & 0x7FFFu);
            for (int e = off; e < end; e++)
                atomicMin(&s_colmin[(unsigned)s_cand[e] & 8191u], (unsigned)k);
        }
        if (tid == 0) s_na[par] = 0;
        __syncthreads();

        // pass B: confirm min-key unclaimed candidate if min registrant.
        for (int i = tid; i < n; i += 1024) {
            const int k = cur[i];
            const int off = (int)(s_meta[k] & 0x7FFFu);
            const int end = (int)(s_meta[k + 1] & 0x7FFFu);
            unsigned long long best = ~0ULL;
            int bestE = -1;
            for (int e = off; e < end; e++) {
                const unsigned long long cd = s_cand[e];
                const unsigned j = (unsigned)cd & 8191u;
                if (!((s_claim[j >> 5] >> (j & 31u)) & 1u) && cd < best) {
                    best = cd;
                    bestE = e;
                }
            }
            if (best == ~0ULL) {
                s_res[k] = 0xFFFFu;                 // unmatched
            } else {
                const unsigned j = (unsigned)best & 8191u;
                if (s_colmin[j] == (unsigned)k) {
                    atomicOr(&s_claim[j >> 5], 1u << (j & 31u));
                    s_res[k] = (unsigned short)bestE;
                } else {
                    nxt[atomicAdd(&s_na[par], 1)] = (unsigned short)k;
                }
            }
        }
        __syncthreads();

        // pass C: incremental colmin clear for all columns touched this round.
        for (int i = tid; i < n; i += 1024) {
            const int k = cur[i];
            const int off = (int)(s_meta[k] & 0x7FFFu);
            const int end = (int)(s_meta[k + 1] & 0x7FFFu);
            for (int e = off; e < end; e++)
                s_colmin[(unsigned)s_cand[e] & 8191u] = 0xFFFFFFFFu;
        }
        __syncthreads();

        n = s_na[par];
        par ^= 1;
        unsigned short* tmp = cur; cur = nxt; nxt = tmp;
    }

    // --- deterministic fixed-order accumulation ---
    const float* truf  = (const float*)tru;
    const float* predf = (const float*)pred;
    float sd = 0.0f, sp = 0.0f;
    int nm = 0;
    for (int k = tid; k < ncomp; k += 1024) {
        const unsigned short r = s_res[k];
        if (r == 0xFFFFu) continue;
        const unsigned long long best = s_cand[r];
        const unsigned m0 = s_meta[k];
        const int row = (int)(m0 >> 15);
        const unsigned j = (unsigned)best & 8191u;
        sd += __uint_as_float((unsigned)(best >> 13));
        nm++;
        const float dp = truf[4 * row + 3] - predf[4 * j + 3];
        sp = fmaf(dp, dp, sp);
    }
#pragma unroll
    for (int o = 16; o > 0; o >>= 1) {
        sd += __shfl_down_sync(0xFFFFFFFFu, sd, o);
        sp += __shfl_down_sync(0xFFFFFFFFu, sp, o);
        nm += __shfl_down_sync(0xFFFFFFFFu, nm, o);
    }
    if (lane == 0) { s_rd[wid] = sd; s_rp[wid] = sp; s_rn[wid] = nm; }
    __syncthreads();
    if (tid == 0) {
        float tsd = 0.0f, tsp = 0.0f;
        int tnm = 0;
        for (int w = 0; w < 32; w++) { tsd += s_rd[w]; tsp += s_rp[w]; tnm += s_rn[w]; }
        const float fnm = (float)tnm;
        const float unm = (float)g_occ - fnm;
        const float mean_dist = tsd / fnm;
        const float prob_mse  = tsp / fnm;
        out[0] = (mean_dist + 10.0f * unm) + (prob_mse + unm);
    }
}

// ---------------------------------------------------------------------------
extern "C" void kernel_launch(void* const* d_in, const int* in_sizes, int n_in,
                              void* d_out, int out_size) {
    const float4* pred = (const float4*)d_in[0];
    const float4* tru  = (const float4*)d_in[1];
    float* out = (float*)d_out;

    void* ccp = nullptr;
    cudaGetSymbolAddress(&ccp, g_cellcnt);
    cudaMemsetAsync(ccp, 0, NCELL * sizeof(int));

    bin_points<<<32, 256>>>(pred);
    build_cand<<<1024, 256>>>(tru);

    cudaFuncSetAttribute(greedy_match, cudaFuncAttributeMaxDynamicSharedMemorySize,
                         SMEM_BYTES);
    greedy_match<<<1, 1024, SMEM_BYTES>>>(pred, tru, out);
}

// round 7
// speedup vs baseline: 17.3157x; 1.1988x over previous
#include <cuda_runtime.h>

#define NT 8192          // true rows
#define NP 8192          // pred cols
#define CAPR 31          // max candidates kept per row (fits 5-bit cnt field)
#define MAXC 12288       // max total compacted candidates (expected ~8.8K)
#define NCELL 8000       // 20x20x20 unit cells
#define CELLCAP 16       // slots per cell (lambda ~0.51 occupied/cell)

// Scratch (device globals — allocation-free; zero-initialized at module load,
// and greedy_match re-zeroes g_cellcnt at the end of every run).
__device__ int g_cellcnt[NCELL];
__device__ float4 g_pts[NCELL * CELLCAP];       // xyz + pred index as int bits
__device__ unsigned long long g_pack;           // hi32 = ngroups, lo32 = ncand total
__device__ unsigned g_meta[NT];                 // row<<19 | cnt<<14 | offset
__device__ unsigned long long g_ccand[MAXC];    // key = (f32bits(d) << 13) | j
__device__ int g_occ;                           // count of occupied true points

__device__ __forceinline__ int cell_of(float x, float y, float z) {
    const int cx = min(19, (int)x);
    const int cy = min(19, (int)y);
    const int cz = min(19, (int)z);
    return (cx * 20 + cy) * 20 + cz;
}

// ---------------------------------------------------------------------------
// Phase 1a: bin occupied preds into fixed-capacity cells; reset run counters.
// ---------------------------------------------------------------------------
__global__ __launch_bounds__(256) void bin_points(const float4* __restrict__ pred) {
    const int i = blockIdx.x * 256 + threadIdx.x;
    if (i == 0) { g_pack = 0ULL; g_occ = 0; }
    const float4 p = pred[i];
    if (p.w >= 0.5f) {
        const int c = cell_of(p.x, p.y, p.z);
        const int idx = atomicAdd(&g_cellcnt[c], 1);
        if (idx < CELLCAP)
            g_pts[c * CELLCAP + idx] = make_float4(p.x, p.y, p.z, __int_as_float(i));
    }
}

// ---------------------------------------------------------------------------
// Phase 1b: candidate generation, WARP per true row; lane L<27 owns one of the
// 3x3x3 neighbor cells. Candidates staged in smem, then the warp reserves a
// (group, offset) pair with ONE packed 64-bit atomic and stores coalesced.
// Also accumulates true-occupancy into g_occ (ONE per occupied row: lane 0).
// ---------------------------------------------------------------------------
#define WPB 8   // warps per block
__global__ __launch_bounds__(256) void build_cand(const float4* __restrict__ tru) {
    __shared__ unsigned long long stage[WPB][32];
    __shared__ int s_cnt[WPB];
    __shared__ int s_occ;
    const int wip  = threadIdx.x >> 5;
    const int lane = threadIdx.x & 31;
    const int row  = blockIdx.x * WPB + wip;

    if (threadIdx.x == 0) s_occ = 0;
    if (lane == 0) s_cnt[wip] = 0;
    __syncthreads();

    const float4 t = tru[row];
    const bool occ = (t.w >= 0.5f);

    if (occ && lane < 27) {
        const int cx = min(19, (int)t.x);
        const int cy = min(19, (int)t.y);
        const int cz = min(19, (int)t.z);
        const int X = cx + lane / 9 - 1;
        const int Y = cy + (lane / 3) % 3 - 1;
        const int Z = cz + lane % 3 - 1;
        if (X >= 0 && X < 20 && Y >= 0 && Y < 20 && Z >= 0 && Z < 20) {
            const int c = (X * 20 + Y) * 20 + Z;
            const int cnt = min(g_cellcnt[c], CELLCAP);
            for (int e = 0; e < cnt; e++) {
                const float4 p = g_pts[c * CELLCAP + e];
                const float dx = t.x - p.x, dy = t.y - p.y, dz = t.z - p.z;
                float d2 = dx * dx;
                d2 = fmaf(dy, dy, d2);
                d2 = fmaf(dz, dz, d2);
                if (d2 <= 1.0000002f) {
                    const float d = __fsqrt_rn(d2);
                    if (d <= 1.0f) {
                        const int idx = atomicAdd(&s_cnt[wip], 1);
                        if (idx < CAPR)
                            stage[wip][idx] =
                                (((unsigned long long)__float_as_uint(d)) << 13) |
                                (unsigned)__float_as_int(p.w);
                    }
                }
            }
        }
    }
    __syncwarp();

    const int cnt = min(s_cnt[wip], CAPR);
    int base = 0;
    if (lane == 0 && cnt > 0) {
        const unsigned long long old =
            atomicAdd(&g_pack, (1ULL << 32) | (unsigned long long)(unsigned)cnt);
        const unsigned gidx = (unsigned)(old >> 32);
        base = (int)(old & 0xFFFFFFFFu);
        const int wcnt = (base + cnt <= MAXC) ? cnt : 0;   // overflow guard (p~0)
        g_meta[gidx] = ((unsigned)row << 19) | ((unsigned)wcnt << 14) |
                       (unsigned)(base & 16383);
    }
    base = __shfl_sync(0xFFFFFFFFu, base, 0);
    if (lane < cnt && base + lane < MAXC) g_ccand[base + lane] = stage[wip][lane];

    // ONE count per occupied row (warp-per-row: lane 0 only!)
    if (lane == 0 && occ) atomicAdd(&s_occ, 1);
    __syncthreads();
    if (threadIdx.x == 0 && s_occ) atomicAdd(&g_occ, s_occ);
}

// ---------------------------------------------------------------------------
// Phase 2: bulk-copy compacted candidates into smem, then PARALLEL round-based
// greedy with ping-pong active lists. Priority = row index (monotone in the
// reference scan order). A group confirms its min-key unclaimed candidate j
// iff colmin[j]==row, i.e. no earlier unresolved row holds j as a candidate.
//
// Dynamic smem layout (bytes):
//   [0,      98304)  s_cand   u64[12288]
//   [98304,  131072) s_meta   u32[8192]   (row<<19 | cnt<<14 | offset)
//   [131072, 163840) s_colmin u32[8192]
//   [163840, 164864) s_claim  u32[256]
//   [164864, 164872) s_na     i32[2]
//   [164872, 165256) s_rd/s_rp/s_rn reduction [32] each
//   [165256, 198024) s_listA/s_listB u16[8192] each
//   [198024, 214408) s_res    u16[8192]   (cand index, 0xFFFF = unmatched)
// ---------------------------------------------------------------------------
#define SMEM_BYTES 214432

__global__ __launch_bounds__(1024, 1) void greedy_match(const float4* __restrict__ pred,
                                                        const float4* __restrict__ tru,
                                                        float* __restrict__ out) {
    extern __shared__ unsigned char sm[];
    unsigned long long* s_cand   = (unsigned long long*)sm;
    unsigned*           s_meta   = (unsigned*)(sm + 98304);
    unsigned*           s_colmin = (unsigned*)(sm + 131072);
    unsigned*           s_claim  = (unsigned*)(sm + 163840);
    int*                s_na     = (int*)(sm + 164864);
    float*              s_rd     = (float*)(sm + 164872);
    float*              s_rp     = (float*)(sm + 165000);
    int*                s_rn     = (int*)(sm + 165128);
    unsigned short*     s_listA  = (unsigned short*)(sm + 165256);
    unsigned short*     s_listB  = (unsigned short*)(sm + 181640);
    unsigned short*     s_res    = (unsigned short*)(sm + 198024);

    const int tid  = threadIdx.x;
    const int lane = tid & 31;
    const int wid  = tid >> 5;

    const unsigned long long pack = g_pack;
    const int ngrp = (int)(pack >> 32);
    const int ctot = min((int)(pack & 0xFFFFFFFFu), MAXC);

    // --- bulk coalesced load of compacted state ---
    for (int i = tid; i < ctot; i += 1024) s_cand[i] = g_ccand[i];
    for (int g = tid; g < ngrp; g += 1024) {
        s_meta[g] = g_meta[g];
        s_listA[g] = (unsigned short)g;
    }
    if (tid < 256) s_claim[tid] = 0u;
    for (int i = tid; i < NP; i += 1024) s_colmin[i] = 0xFFFFFFFFu;
    __syncthreads();

    unsigned short* cur = s_listA;
    unsigned short* nxt = s_listB;
    int n = ngrp;
    int par = 0;
    while (n > 0) {
        // pass A: each active row registers on ALL its candidate columns.
        for (int i = tid; i < n; i += 1024) {
            const unsigned m = s_meta[cur[i]];
            const unsigned row = m >> 19;
            const int off = (int)(m & 16383u);
            const int end = off + (int)((m >> 14) & 31u);
            for (int e = off; e < end; e++)
                atomicMin(&s_colmin[(unsigned)s_cand[e] & 8191u], row);
        }
        if (tid == 0) s_na[par] = 0;
        __syncthreads();

        // pass B: confirm min-key unclaimed candidate if min registrant.
        for (int i = tid; i < n; i += 1024) {
            const int g = cur[i];
            const unsigned m = s_meta[g];
            const unsigned row = m >> 19;
            const int off = (int)(m & 16383u);
            const int end = off + (int)((m >> 14) & 31u);
            unsigned long long best = ~0ULL;
            int bestE = -1;
            for (int e = off; e < end; e++) {
                const unsigned long long cd = s_cand[e];
                const unsigned j = (unsigned)cd & 8191u;
                if (!((s_claim[j >> 5] >> (j & 31u)) & 1u) && cd < best) {
                    best = cd;
                    bestE = e;
                }
            }
            if (best == ~0ULL) {
                s_res[g] = 0xFFFFu;                 // unmatched
            } else {
                const unsigned j = (unsigned)best & 8191u;
                if (s_colmin[j] == row) {
                    atomicOr(&s_claim[j >> 5], 1u << (j & 31u));
                    s_res[g] = (unsigned short)bestE;
                } else {
                    nxt[atomicAdd(&s_na[par], 1)] = (unsigned short)g;
                }
            }
        }
        __syncthreads();

        // pass C: incremental colmin clear for all columns touched this round.
        for (int i = tid; i < n; i += 1024) {
            const unsigned m = s_meta[cur[i]];
            const int off = (int)(m & 16383u);
            const int end = off + (int)((m >> 14) & 31u);
            for (int e = off; e < end; e++)
                s_colmin[(unsigned)s_cand[e] & 8191u] = 0xFFFFFFFFu;
        }
        __syncthreads();

        n = s_na[par];
        par ^= 1;
        unsigned short* tmp = cur; cur = nxt; nxt = tmp;
    }

    // --- fixed-order accumulation ---
    const float* truf  = (const float*)tru;
    const float* predf = (const float*)pred;
    float sd = 0.0f, sp = 0.0f;
    int nm = 0;
    for (int g = tid; g < ngrp; g += 1024) {
        const unsigned short r = s_res[g];
        if (r == 0xFFFFu) continue;
        const unsigned long long best = s_cand[r];
        const unsigned row = s_meta[g] >> 19;
        const unsigned j = (unsigned)best & 8191u;
        sd += __uint_as_float((unsigned)(best >> 13));
        nm++;
        const float dp = truf[4 * row + 3] - predf[4 * j + 3];
        sp = fmaf(dp, dp, sp);
    }
#pragma unroll
    for (int o = 16; o > 0; o >>= 1) {
        sd += __shfl_down_sync(0xFFFFFFFFu, sd, o);
        sp += __shfl_down_sync(0xFFFFFFFFu, sp, o);
        nm += __shfl_down_sync(0xFFFFFFFFu, nm, o);
    }
    if (lane == 0) { s_rd[wid] = sd; s_rp[wid] = sp; s_rn[wid] = nm; }

    // re-zero the cell counters for the next replay (graph-deterministic)
    for (int i = tid; i < NCELL; i += 1024) g_cellcnt[i] = 0;

    __syncthreads();
    if (tid == 0) {
        float tsd = 0.0f, tsp = 0.0f;
        int tnm = 0;
        for (int w = 0; w < 32; w++) { tsd += s_rd[w]; tsp += s_rp[w]; tnm += s_rn[w]; }
        const float fnm = (float)tnm;
        const float unm = (float)g_occ - fnm;
        const float mean_dist = tsd / fnm;
        const float prob_mse  = tsp / fnm;
        out[0] = (mean_dist + 10.0f * unm) + (prob_mse + unm);
    }
}

// ---------------------------------------------------------------------------
extern "C" void kernel_launch(void* const* d_in, const int* in_sizes, int n_in,
                              void* d_out, int out_size) {
    const float4* pred = (const float4*)d_in[0];
    const float4* tru  = (const float4*)d_in[1];
    float* out = (float*)d_out;

    bin_points<<<32, 256>>>(pred);
    build_cand<<<1024, 256>>>(tru);

    cudaFuncSetAttribute(greedy_match, cudaFuncAttributeMaxDynamicSharedMemorySize,
                         SMEM_BYTES);
    greedy_match<<<1, 1024, SMEM_BYTES>>>(pred, tru, out);
}

// round 8
// speedup vs baseline: 19.7579x; 1.1410x over previous
#include <cuda_runtime.h>

#define NT 8192          // true rows
#define NP 8192          // pred cols
#define CAPR 31          // max candidates kept per row (fits 5-bit cnt field)
#define MAXC 12288       // max total compacted candidates (expected ~8.8K)
#define NCELL 8000       // 20x20x20 unit cells
#define CELLCAP 16       // slots per cell (lambda ~0.51 occupied/cell)

// Scratch (device globals — allocation-free; zero-initialized at module load,
// and greedy_match re-zeroes g_cellcnt at the end of every run).
__device__ int g_cellcnt[NCELL];
__device__ float4 g_pts[NCELL * CELLCAP];       // xyz + pred index as int bits
__device__ unsigned long long g_pack;           // hi32 = ngroups, lo32 = ncand total
__device__ unsigned g_meta[NT];                 // row<<19 | cnt<<14 | offset
__device__ unsigned long long g_ccand[MAXC];    // key = (f32bits(d) << 13) | j
__device__ int g_occ;                           // count of occupied true points

__device__ __forceinline__ int cell_of(float x, float y, float z) {
    const int cx = min(19, (int)x);
    const int cy = min(19, (int)y);
    const int cz = min(19, (int)z);
    return (cx * 20 + cy) * 20 + cz;
}

// ---------------------------------------------------------------------------
// Phase 1a: bin occupied preds into fixed-capacity cells; reset run counters.
// ---------------------------------------------------------------------------
__global__ __launch_bounds__(256) void bin_points(const float4* __restrict__ pred) {
    const int i = blockIdx.x * 256 + threadIdx.x;
    if (i == 0) { g_pack = 0ULL; g_occ = 0; }
    const float4 p = pred[i];
    if (p.w >= 0.5f) {
        const int c = cell_of(p.x, p.y, p.z);
        const int idx = atomicAdd(&g_cellcnt[c], 1);
        if (idx < CELLCAP)
            g_pts[c * CELLCAP + idx] = make_float4(p.x, p.y, p.z, __int_as_float(i));
    }
}

// ---------------------------------------------------------------------------
// Phase 1b: candidate generation, WARP per true row; lane L<27 owns one of the
// 3x3x3 neighbor cells. Candidates staged in smem, then the warp reserves a
// (group, offset) pair with ONE packed 64-bit atomic and stores coalesced.
// Also accumulates true-occupancy into g_occ (ONE per occupied row: lane 0).
// ---------------------------------------------------------------------------
#define WPB 8   // warps per block
__global__ __launch_bounds__(256) void build_cand(const float4* __restrict__ tru) {
    __shared__ unsigned long long stage[WPB][32];
    __shared__ int s_cnt[WPB];
    __shared__ int s_occ;
    const int wip  = threadIdx.x >> 5;
    const int lane = threadIdx.x & 31;
    const int row  = blockIdx.x * WPB + wip;

    if (threadIdx.x == 0) s_occ = 0;
    if (lane == 0) s_cnt[wip] = 0;
    __syncthreads();

    const float4 t = tru[row];
    const bool occ = (t.w >= 0.5f);

    if (occ && lane < 27) {
        const int cx = min(19, (int)t.x);
        const int cy = min(19, (int)t.y);
        const int cz = min(19, (int)t.z);
        const int X = cx + lane / 9 - 1;
        const int Y = cy + (lane / 3) % 3 - 1;
        const int Z = cz + lane % 3 - 1;
        if (X >= 0 && X < 20 && Y >= 0 && Y < 20 && Z >= 0 && Z < 20) {
            const int c = (X * 20 + Y) * 20 + Z;
            const int cnt = min(g_cellcnt[c], CELLCAP);
            for (int e = 0; e < cnt; e++) {
                const float4 p = g_pts[c * CELLCAP + e];
                const float dx = t.x - p.x, dy = t.y - p.y, dz = t.z - p.z;
                float d2 = dx * dx;
                d2 = fmaf(dy, dy, d2);
                d2 = fmaf(dz, dz, d2);
                if (d2 <= 1.0000002f) {
                    const float d = __fsqrt_rn(d2);
                    if (d <= 1.0f) {
                        const int idx = atomicAdd(&s_cnt[wip], 1);
                        if (idx < CAPR)
                            stage[wip][idx] =
                                (((unsigned long long)__float_as_uint(d)) << 13) |
                                (unsigned)__float_as_int(p.w);
                    }
                }
            }
        }
    }
    __syncwarp();

    const int cnt = min(s_cnt[wip], CAPR);
    int base = 0;
    if (lane == 0 && cnt > 0) {
        const unsigned long long old =
            atomicAdd(&g_pack, (1ULL << 32) | (unsigned long long)(unsigned)cnt);
        const unsigned gidx = (unsigned)(old >> 32);
        base = (int)(old & 0xFFFFFFFFu);
        const int wcnt = (base + cnt <= MAXC) ? cnt : 0;   // overflow guard (p~0)
        g_meta[gidx] = ((unsigned)row << 19) | ((unsigned)wcnt << 14) |
                       (unsigned)(base & 16383);
    }
    base = __shfl_sync(0xFFFFFFFFu, base, 0);
    if (lane < cnt && base + lane < MAXC) g_ccand[base + lane] = stage[wip][lane];

    // ONE count per occupied row (warp-per-row: lane 0 only!)
    if (lane == 0 && occ) atomicAdd(&s_occ, 1);
    __syncthreads();
    if (threadIdx.x == 0 && s_occ) atomicAdd(&g_occ, s_occ);
}

// ---------------------------------------------------------------------------
// Phase 2: bulk-copy compacted candidates into smem, then PARALLEL round-based
// greedy with ping-pong active lists. Priority = row index (monotone in the
// reference scan order). A group confirms its min-key unclaimed candidate j
// iff colmin[j]==(epoch|row), i.e. no earlier unresolved row registered j
// THIS round. colmin values are epoch-tagged, strictly decreasing per round:
// stale entries from earlier rounds are always LARGER than any current-round
// registration, so they can neither win atomicMin nor fake the equality check
// — no per-round clearing pass needed (2 passes + 2 barriers per round).
//
// Dynamic smem layout (bytes):
//   [0,      98304)  s_cand   u64[12288]
//   [98304,  131072) s_meta   u32[8192]   (row<<19 | cnt<<14 | offset)
//   [131072, 163840) s_colmin u32[8192]   ((0x3FFFF-round)<<13 | row)
//   [163840, 164864) s_claim  u32[256]
//   [164864, 164872) s_na     i32[2]
//   [164872, 165256) s_rd/s_rp/s_rn reduction [32] each
//   [165256, 198024) s_listA/s_listB u16[8192] each
//   [198024, 214408) s_res    u16[8192]   (cand index, 0xFFFF = unmatched)
// ---------------------------------------------------------------------------
#define SMEM_BYTES 214432

__global__ __launch_bounds__(1024, 1) void greedy_match(const float4* __restrict__ pred,
                                                        const float4* __restrict__ tru,
                                                        float* __restrict__ out) {
    extern __shared__ unsigned char sm[];
    unsigned long long* s_cand   = (unsigned long long*)sm;
    unsigned*           s_meta   = (unsigned*)(sm + 98304);
    unsigned*           s_colmin = (unsigned*)(sm + 131072);
    unsigned*           s_claim  = (unsigned*)(sm + 163840);
    int*                s_na     = (int*)(sm + 164864);
    float*              s_rd     = (float*)(sm + 164872);
    float*              s_rp     = (float*)(sm + 165000);
    int*                s_rn     = (int*)(sm + 165128);
    unsigned short*     s_listA  = (unsigned short*)(sm + 165256);
    unsigned short*     s_listB  = (unsigned short*)(sm + 181640);
    unsigned short*     s_res    = (unsigned short*)(sm + 198024);

    const int tid  = threadIdx.x;
    const int lane = tid & 31;
    const int wid  = tid >> 5;

    const unsigned long long pack = g_pack;
    const int ngrp = (int)(pack >> 32);
    const int ctot = min((int)(pack & 0xFFFFFFFFu), MAXC);

    // --- bulk coalesced load of compacted state ---
    for (int i = tid; i < ctot; i += 1024) s_cand[i] = g_ccand[i];
    for (int g = tid; g < ngrp; g += 1024) {
        s_meta[g] = g_meta[g];
        s_listA[g] = (unsigned short)g;
    }
    if (tid < 256) s_claim[tid] = 0u;
    for (int i = tid; i < NP; i += 1024) s_colmin[i] = 0xFFFFFFFFu;
    __syncthreads();

    unsigned short* cur = s_listA;
    unsigned short* nxt = s_listB;
    int n = ngrp;
    int par = 0;
    unsigned round = 0;
    while (n > 0) {
        const unsigned epoch = (0x3FFFFu - round) << 13;   // strictly decreasing

        // pass A: each active row registers (epoch|row) on ALL its candidates.
        for (int i = tid; i < n; i += 1024) {
            const unsigned m = s_meta[cur[i]];
            const unsigned val = epoch | (m >> 19);
            const int off = (int)(m & 16383u);
            const int end = off + (int)((m >> 14) & 31u);
            for (int e = off; e < end; e++)
                atomicMin(&s_colmin[(unsigned)s_cand[e] & 8191u], val);
        }
        if (tid == 0) s_na[par] = 0;
        __syncthreads();

        // pass B: confirm min-key unclaimed candidate if min registrant.
        for (int i = tid; i < n; i += 1024) {
            const int g = cur[i];
            const unsigned m = s_meta[g];
            const unsigned val = epoch | (m >> 19);
            const int off = (int)(m & 16383u);
            const int end = off + (int)((m >> 14) & 31u);
            unsigned long long best = ~0ULL;
            int bestE = -1;
            for (int e = off; e < end; e++) {
                const unsigned long long cd = s_cand[e];
                const unsigned j = (unsigned)cd & 8191u;
                if (!((s_claim[j >> 5] >> (j & 31u)) & 1u) && cd < best) {
                    best = cd;
                    bestE = e;
                }
            }
            if (best == ~0ULL) {
                s_res[g] = 0xFFFFu;                 // unmatched
            } else {
                const unsigned j = (unsigned)best & 8191u;
                if (s_colmin[j] == val) {
                    atomicOr(&s_claim[j >> 5], 1u << (j & 31u));
                    s_res[g] = (unsigned short)bestE;
                } else {
                    nxt[atomicAdd(&s_na[par], 1)] = (unsigned short)g;
                }
            }
        }
        __syncthreads();

        n = s_na[par];
        par ^= 1;
        round++;
        unsigned short* tmp = cur; cur = nxt; nxt = tmp;
    }

    // --- fixed-order accumulation ---
    const float* truf  = (const float*)tru;
    const float* predf = (const float*)pred;
    float sd = 0.0f, sp = 0.0f;
    int nm = 0;
    for (int g = tid; g < ngrp; g += 1024) {
        const unsigned short r = s_res[g];
        if (r == 0xFFFFu) continue;
        const unsigned long long best = s_cand[r];
        const unsigned row = s_meta[g] >> 19;
        const unsigned j = (unsigned)best & 8191u;
        sd += __uint_as_float((unsigned)(best >> 13));
        nm++;
        const float dp = truf[4 * row + 3] - predf[4 * j + 3];
        sp = fmaf(dp, dp, sp);
    }
#pragma unroll
    for (int o = 16; o > 0; o >>= 1) {
        sd += __shfl_down_sync(0xFFFFFFFFu, sd, o);
        sp += __shfl_down_sync(0xFFFFFFFFu, sp, o);
        nm += __shfl_down_sync(0xFFFFFFFFu, nm, o);
    }
    if (lane == 0) { s_rd[wid] = sd; s_rp[wid] = sp; s_rn[wid] = nm; }

    // re-zero the cell counters for the next replay (graph-deterministic)
    for (int i = tid; i < NCELL; i += 1024) g_cellcnt[i] = 0;

    __syncthreads();
    if (tid == 0) {
        float tsd = 0.0f, tsp = 0.0f;
        int tnm = 0;
        for (int w = 0; w < 32; w++) { tsd += s_rd[w]; tsp += s_rp[w]; tnm += s_rn[w]; }
        const float fnm = (float)tnm;
        const float unm = (float)g_occ - fnm;
        const float mean_dist = tsd / fnm;
        const float prob_mse  = tsp / fnm;
        out[0] = (mean_dist + 10.0f * unm) + (prob_mse + unm);
    }
}

// ---------------------------------------------------------------------------
extern "C" void kernel_launch(void* const* d_in, const int* in_sizes, int n_in,
                              void* d_out, int out_size) {
    const float4* pred = (const float4*)d_in[0];
    const float4* tru  = (const float4*)d_in[1];
    float* out = (float*)d_out;

    bin_points<<<32, 256>>>(pred);
    build_cand<<<1024, 256>>>(tru);

    cudaFuncSetAttribute(greedy_match, cudaFuncAttributeMaxDynamicSharedMemorySize,
                         SMEM_BYTES);
    greedy_match<<<1, 1024, SMEM_BYTES>>>(pred, tru, out);
}